// round 16
// baseline (speedup 1.0000x reference)
#include <cuda_runtime.h>
#include <cuda_bf16.h>
#include <cuda_fp16.h>
#include <math.h>
#include <stdint.h>

#define HIDDEN 1024
#define HEADS  16
#define HD     64
#define BATCH  4
#define SEQ    2048
#define MTOT   (BATCH * SEQ)   // 8192

// Q pre-scale: (1/sqrt(64)) * log2(e) -> softmax computed in exp2 domain
#define QSCALE 0.1803368801111244f

// ---------------- scratch (device globals; no allocs allowed) --------------
__device__ __half g_xf[MTOT * HIDDEN];            // activations fp16 (x, then attn out)
__device__ __half g_wq[3 * HIDDEN * HIDDEN];      // W_qkv^T fp16 [3072,1024]
__device__ __half g_wo[HIDDEN * HIDDEN];          // W_out^T fp16 [1024,1024]
__device__ __half g_qf[BATCH * HEADS * SEQ * HD]; // Q (pre-scaled, log2 domain)
__device__ __half g_kf[BATCH * HEADS * SEQ * HD]; // K
__device__ __half g_vth[BATCH * HEADS * HD * SEQ];// V^T

// ---------------- async-copy / ldmatrix helpers -----------------------------
__device__ __forceinline__ void cp_async16(uint32_t saddr, const void* gptr) {
    asm volatile("cp.async.ca.shared.global [%0], [%1], 16;"
                 :: "r"(saddr), "l"(gptr));
}
#define CP_COMMIT()  asm volatile("cp.async.commit_group;" ::: "memory")
#define CP_WAIT(n)   asm volatile("cp.async.wait_group %0;" :: "n"(n) : "memory")

__device__ __forceinline__ void ldsm4(uint32_t* r, uint32_t addr) {
    asm volatile("ldmatrix.sync.aligned.m8n8.x4.shared.b16 {%0,%1,%2,%3}, [%4];"
                 : "=r"(r[0]), "=r"(r[1]), "=r"(r[2]), "=r"(r[3]) : "r"(addr));
}

// ---------------------------------------------------------------------------
__global__ __launch_bounds__(256) void cast_kernel(
    const float* __restrict__ src, __half* __restrict__ dst, int n4)
{
    int i = blockIdx.x * blockDim.x + threadIdx.x;
    if (i >= n4) return;
    float4 v = ((const float4*)src)[i];
    ((__half2*)dst)[2 * i]     = __floats2half2_rn(v.x, v.y);
    ((__half2*)dst)[2 * i + 1] = __floats2half2_rn(v.z, v.w);
}

// transpose + cast: W[K,N] fp32 -> W^T fp16 [N,K]
__global__ void tcast_kernel(const float* __restrict__ W,
                             __half* __restrict__ Wt, int K, int N)
{
    __shared__ float t[32][33];
    int n0 = blockIdx.x * 32, k0 = blockIdx.y * 32;
    for (int r = threadIdx.y; r < 32; r += 8)
        t[r][threadIdx.x] = W[(size_t)(k0 + r) * N + n0 + threadIdx.x];
    __syncthreads();
    for (int r = threadIdx.y; r < 32; r += 8)
        Wt[(size_t)(n0 + r) * K + k0 + threadIdx.x] =
            __float2half_rn(t[threadIdx.x][r]);
}

// ---------------------------------------------------------------------------
__device__ __forceinline__ void mma16816h(float* c, const uint32_t* a, const uint32_t* b)
{
    asm volatile(
        "mma.sync.aligned.m16n8k16.row.col.f32.f16.f16.f32 "
        "{%0,%1,%2,%3}, {%4,%5,%6,%7}, {%8,%9}, {%0,%1,%2,%3};"
        : "+f"(c[0]), "+f"(c[1]), "+f"(c[2]), "+f"(c[3])
        : "r"(a[0]), "r"(a[1]), "r"(a[2]), "r"(a[3]), "r"(b[0]), "r"(b[1]));
}

// ---------------------------------------------------------------------------
// HMMA GEMM (single-pass fp16): C[M,N] = A @ W^T + bias.
// CTA 128x128, 8 warps (2 over M x 4 over N), warp tile 64x32.
// 256 threads, regs <= 128 -> 2 CTAs/SM = 16 warps/SM.
// cp.async 2-stage + ldmatrix.
// mode 0: C + bias (fp32). mode 1: QKV epilogue (Q scaled log2-domain, K, V^T).
// per stage: A=0 (10240B), B=10240; stage stride 20480.
// ---------------------------------------------------------------------------
#define SPAD 40
#define GST  20480
#define GEMM_SMEM (2 * GST)

__global__ __launch_bounds__(256, 2) void hmma_gemm(
    const __half* __restrict__ A, const __half* __restrict__ B,
    const float* __restrict__ bias, float* __restrict__ C,
    __half* __restrict__ qf, __half* __restrict__ kf,
    __half* __restrict__ vth,
    int M, int N, int K, int mode)
{
    extern __shared__ char smem[];
    const uint32_t sbase = (uint32_t)__cvta_generic_to_shared(smem);

    const int tid  = threadIdx.x;
    const int wid  = tid >> 5;
    const int lane = tid & 31;
    const int grp  = lane >> 2;
    const int tig  = lane & 3;
    const int wm   = wid & 1;          // 2 warps over M (64 rows)
    const int wn   = wid >> 1;         // 4 warps over N (32 cols)
    const int bm   = blockIdx.y * 128;
    const int bn   = blockIdx.x * 128;
    const int NT   = K / 32;

    const int mat = lane >> 3, lr = lane & 7;
    const int a_row = (mat & 1) * 8 + lr;
    const int a_col = (mat >> 1) * 8;
    const int b_jo  = mat >> 1;
    const int b_col = (mat & 1) * 8;

    float c[4][4][4];
    #pragma unroll
    for (int i = 0; i < 4; i++)
        #pragma unroll
        for (int j = 0; j < 4; j++)
            #pragma unroll
            for (int p = 0; p < 4; p++) c[i][j][p] = 0.f;

    auto issue_tile = [&](int kt, int stage) {
        const int k0 = kt * 32;
        const uint32_t st = sbase + stage * GST;
        #pragma unroll
        for (int u = 0; u < 2; u++) {
            int g = tid + u * 256;          // 0..511
            int r = g >> 2, ch = g & 3;
            uint32_t so = (uint32_t)(r * SPAD + ch * 8) * 2;
            cp_async16(st + so,         A + (size_t)(bm + r) * K + k0 + ch * 8);
            cp_async16(st + 10240 + so, B + (size_t)(bn + r) * K + k0 + ch * 8);
        }
        CP_COMMIT();
    };

    issue_tile(0, 0);

    for (int kt = 0; kt < NT; kt++) {
        if (kt + 1 < NT) {
            issue_tile(kt + 1, (kt + 1) & 1);
            CP_WAIT(1);
        } else {
            CP_WAIT(0);
        }
        __syncthreads();

        const uint32_t st = sbase + (kt & 1) * GST;

        #pragma unroll
        for (int ks = 0; ks < 2; ks++) {
            const int kk = ks * 16;
            uint32_t af[4][4], bf[2][4];
            #pragma unroll
            for (int i = 0; i < 4; i++) {
                uint32_t ad = st + (uint32_t)((wm * 64 + i * 16 + a_row) * SPAD + kk + a_col) * 2;
                ldsm4(af[i], ad);
            }
            #pragma unroll
            for (int p = 0; p < 2; p++) {
                uint32_t bd = st + 10240 +
                    (uint32_t)((wn * 32 + (p * 2 + b_jo) * 8 + lr) * SPAD + kk + b_col) * 2;
                ldsm4(bf[p], bd);
            }
            #pragma unroll
            for (int i = 0; i < 4; i++)
                #pragma unroll
                for (int j = 0; j < 4; j++)
                    mma16816h(c[i][j], af[i], &bf[j >> 1][(j & 1) * 2]);
        }
        __syncthreads();
    }

    #pragma unroll
    for (int i = 0; i < 4; i++) {
        #pragma unroll
        for (int j = 0; j < 4; j++) {
            int n0 = bn + wn * 32 + j * 8 + tig * 2;
            float2 bv = *(const float2*)(bias + n0);
            #pragma unroll
            for (int half = 0; half < 2; half++) {
                int m = bm + wm * 64 + i * 16 + grp + half * 8;
                float rx = c[i][j][half * 2 + 0] + bv.x;
                float ry = c[i][j][half * 2 + 1] + bv.y;
                if (mode == 0) {
                    *(float2*)(C + (size_t)m * N + n0) = make_float2(rx, ry);
                } else {
                    int sel = n0 >> 10, rem = n0 & 1023;
                    int h = rem >> 6, hd0 = rem & 63;
                    int b = m >> 11, s = m & 2047;
                    size_t bh_ = (size_t)b * HEADS + h;
                    if (sel == 0) {
                        size_t off = (bh_ * SEQ + s) * HD + hd0;
                        *(__half2*)(qf + off) =
                            __floats2half2_rn(rx * QSCALE, ry * QSCALE);
                    } else if (sel == 1) {
                        size_t off = (bh_ * SEQ + s) * HD + hd0;
                        *(__half2*)(kf + off) = __floats2half2_rn(rx, ry);
                    } else {
                        size_t o0 = (bh_ * HD + hd0) * SEQ + s;
                        size_t o1 = (bh_ * HD + hd0 + 1) * SEQ + s;
                        vth[o0] = __float2half_rn(rx);
                        vth[o1] = __float2half_rn(ry);
                    }
                }
            }
        }
    }
}

// ---------------------------------------------------------------------------
// fp16 HMMA flash attention (exp2 domain): 128 q-rows/CTA, 8 warps x 16
// q-rows, 64-key tiles, cp.async 2-stage + ldmatrix, 2 CTAs/SM.
// S' = (Q*log2e/8) * K ; P = exp2(S' - m'). Output fp16 [B,S,H*64].
// per stage: K=0 (9216B), V=9216; stage stride 18432.
// ---------------------------------------------------------------------------
#define KPITCH 72
#define AST    18432
#define ATTN_SMEM (2 * AST)

__global__ __launch_bounds__(256, 2) void attn_hmma(
    const __half* __restrict__ qf, const __half* __restrict__ kf,
    const __half* __restrict__ vth,
    __half* __restrict__ O)
{
    extern __shared__ char smem[];
    const uint32_t sbase = (uint32_t)__cvta_generic_to_shared(smem);

    const int tid  = threadIdx.x;
    const int wid  = tid >> 5;
    const int lane = tid & 31;
    const int grp  = lane >> 2;
    const int tig  = lane & 3;
    const int bh   = blockIdx.y;
    const int q0   = blockIdx.x * 128;

    const int mat = lane >> 3, lr = lane & 7;
    const int b_jo  = mat >> 1;
    const int b_col = (mat & 1) * 8;

    const __half* Kb = kf + (size_t)bh * SEQ * HD;
    const __half* Vb = vth + (size_t)bh * HD * SEQ;

    auto issue_tile = [&](int kt, int stage) {
        const uint32_t st = sbase + stage * AST;
        #pragma unroll
        for (int i = 0; i < 2; i++) {
            int g = tid + i * 256;
            int r = g >> 3, ch = g & 7;
            uint32_t so = (uint32_t)(r * KPITCH + ch * 8) * 2;
            cp_async16(st + so,        Kb + (size_t)(kt * 64 + r) * HD + ch * 8);
            cp_async16(st + 9216 + so, Vb + (size_t)r * SEQ + kt * 64 + ch * 8);
        }
        CP_COMMIT();
    };

    issue_tile(0, 0);

    uint32_t qfr[4][4];
    {
        const __half* Qp = qf + ((size_t)bh * SEQ + q0 + wid * 16) * HD;
        #pragma unroll
        for (int cc = 0; cc < 4; cc++) {
            int k0 = cc * 16 + 2 * tig;
            qfr[cc][0] = *(const uint32_t*)(Qp + grp * HD + k0);
            qfr[cc][1] = *(const uint32_t*)(Qp + (grp + 8) * HD + k0);
            qfr[cc][2] = *(const uint32_t*)(Qp + grp * HD + k0 + 8);
            qfr[cc][3] = *(const uint32_t*)(Qp + (grp + 8) * HD + k0 + 8);
        }
    }

    float o[8][4];
    #pragma unroll
    for (int j = 0; j < 8; j++)
        #pragma unroll
        for (int p = 0; p < 4; p++) o[j][p] = 0.f;
    float m0 = -INFINITY, m1 = -INFINITY, l0 = 0.f, l1 = 0.f;

    const int NT = SEQ / 64;
    for (int kt = 0; kt < NT; kt++) {
        if (kt + 1 < NT) {
            issue_tile(kt + 1, (kt + 1) & 1);
            CP_WAIT(1);
        } else {
            CP_WAIT(0);
        }
        __syncthreads();

        const uint32_t st = sbase + (kt & 1) * AST;

        // ---- S' = Q*K (log2 domain) ----
        float s[8][4];
        #pragma unroll
        for (int j = 0; j < 8; j++)
            #pragma unroll
            for (int p = 0; p < 4; p++) s[j][p] = 0.f;
        #pragma unroll
        for (int cc = 0; cc < 4; cc++) {
            #pragma unroll
            for (int p = 0; p < 4; p++) {
                uint32_t kfr[4];
                uint32_t kd = st + (uint32_t)(((p * 2 + b_jo) * 8 + lr) * KPITCH
                                              + cc * 16 + b_col) * 2;
                ldsm4(kfr, kd);
                mma16816h(s[2 * p],     qfr[cc], &kfr[0]);
                mma16816h(s[2 * p + 1], qfr[cc], &kfr[2]);
            }
        }

        // ---- online softmax (exp2) ----
        float mx0 = -INFINITY, mx1 = -INFINITY;
        #pragma unroll
        for (int j = 0; j < 8; j++) {
            mx0 = fmaxf(mx0, fmaxf(s[j][0], s[j][1]));
            mx1 = fmaxf(mx1, fmaxf(s[j][2], s[j][3]));
        }
        mx0 = fmaxf(mx0, __shfl_xor_sync(0xffffffffu, mx0, 1));
        mx0 = fmaxf(mx0, __shfl_xor_sync(0xffffffffu, mx0, 2));
        mx1 = fmaxf(mx1, __shfl_xor_sync(0xffffffffu, mx1, 1));
        mx1 = fmaxf(mx1, __shfl_xor_sync(0xffffffffu, mx1, 2));
        float mn0 = fmaxf(m0, mx0), mn1 = fmaxf(m1, mx1);
        float a0 = exp2f(m0 - mn0), a1 = exp2f(m1 - mn1);
        m0 = mn0; m1 = mn1;

        uint32_t pfr[4][4];
        float ps0 = 0.f, ps1 = 0.f;
        #pragma unroll
        for (int j = 0; j < 8; j++) {
            float p0 = exp2f(s[j][0] - m0);
            float p1 = exp2f(s[j][1] - m0);
            float p2 = exp2f(s[j][2] - m1);
            float p3 = exp2f(s[j][3] - m1);
            ps0 += p0 + p1;
            ps1 += p2 + p3;
            int cc = j >> 1, half = j & 1;
            __half2 pa = __floats2half2_rn(p0, p1);
            __half2 pb = __floats2half2_rn(p2, p3);
            pfr[cc][0 + 2 * half] = *(uint32_t*)&pa;
            pfr[cc][1 + 2 * half] = *(uint32_t*)&pb;
        }
        ps0 += __shfl_xor_sync(0xffffffffu, ps0, 1);
        ps0 += __shfl_xor_sync(0xffffffffu, ps0, 2);
        ps1 += __shfl_xor_sync(0xffffffffu, ps1, 1);
        ps1 += __shfl_xor_sync(0xffffffffu, ps1, 2);
        l0 = l0 * a0 + ps0;
        l1 = l1 * a1 + ps1;

        #pragma unroll
        for (int j = 0; j < 8; j++) {
            o[j][0] *= a0; o[j][1] *= a0;
            o[j][2] *= a1; o[j][3] *= a1;
        }

        // ---- O += P*V ----
        #pragma unroll
        for (int cc = 0; cc < 4; cc++) {
            #pragma unroll
            for (int p = 0; p < 4; p++) {
                uint32_t vfr[4];
                uint32_t vd = st + 9216 +
                    (uint32_t)(((p * 2 + b_jo) * 8 + lr) * KPITCH + cc * 16 + b_col) * 2;
                ldsm4(vfr, vd);
                mma16816h(o[2 * p],     pfr[cc], &vfr[0]);
                mma16816h(o[2 * p + 1], pfr[cc], &vfr[2]);
            }
        }
        __syncthreads();
    }

    // ---- epilogue: O / l, single fp16 into [B,S,H*64] ----
    const int b = bh >> 4;
    const int h = bh & 15;
    float inv0 = 1.0f / l0, inv1 = 1.0f / l1;
    int s0 = q0 + wid * 16 + grp;
    int s1 = s0 + 8;
    #pragma unroll
    for (int j = 0; j < 8; j++) {
        int col = h * HD + j * 8 + 2 * tig;
        size_t off0 = ((size_t)b * SEQ + s0) * HIDDEN + col;
        *(__half2*)(O + off0) = __floats2half2_rn(o[j][0] * inv0, o[j][1] * inv0);
        size_t off1 = ((size_t)b * SEQ + s1) * HIDDEN + col;
        *(__half2*)(O + off1) = __floats2half2_rn(o[j][2] * inv1, o[j][3] * inv1);
    }
}

// ---------------------------------------------------------------------------
extern "C" void kernel_launch(void* const* d_in, const int* in_sizes, int n_in,
                              void* d_out, int out_size)
{
    const float* x     = (const float*)d_in[0];
    const float* W_qkv = (const float*)d_in[1];
    const float* b_qkv = (const float*)d_in[2];
    const float* W_out = (const float*)d_in[3];
    const float* b_out = (const float*)d_in[4];
    float* out = (float*)d_out;

    static __half *pxf = nullptr, *pwq, *pwo;
    static __half *pqf, *pkf, *pvth;
    if (!pxf) {
        cudaGetSymbolAddress((void**)&pxf, g_xf);
        cudaGetSymbolAddress((void**)&pwq, g_wq);
        cudaGetSymbolAddress((void**)&pwo, g_wo);
        cudaGetSymbolAddress((void**)&pqf, g_qf);
        cudaGetSymbolAddress((void**)&pkf, g_kf);
        cudaGetSymbolAddress((void**)&pvth, g_vth);
        cudaFuncSetAttribute(hmma_gemm, cudaFuncAttributeMaxDynamicSharedMemorySize, GEMM_SMEM);
        cudaFuncSetAttribute(attn_hmma, cudaFuncAttributeMaxDynamicSharedMemorySize, ATTN_SMEM);
    }

    const int n4 = MTOT * HIDDEN / 4;

    // 1) cast x -> fp16; transpose+cast weights -> fp16
    cast_kernel<<<n4 / 256, 256>>>(x, pxf, n4);
    {
        dim3 g(3 * HIDDEN / 32, HIDDEN / 32);
        tcast_kernel<<<g, dim3(32, 8)>>>(W_qkv, pwq, HIDDEN, 3 * HIDDEN);
    }
    {
        dim3 g(HIDDEN / 32, HIDDEN / 32);
        tcast_kernel<<<g, dim3(32, 8)>>>(W_out, pwo, HIDDEN, HIDDEN);
    }

    // 2) QKV projection (fp16 single-pass HMMA, 16 warps/SM) -> Q/K/V fp16
    {
        dim3 g(3 * HIDDEN / 128, MTOT / 128);   // (24, 64)
        hmma_gemm<<<g, 256, GEMM_SMEM>>>(pxf, pwq, b_qkv, nullptr,
                                         pqf, pkf, pvth,
                                         MTOT, 3 * HIDDEN, HIDDEN, 1);
    }

    // 3) fp16 flash attention (exp2 domain) -> fp16 activations
    {
        dim3 g(SEQ / 128, BATCH * HEADS);       // (16, 64)
        attn_hmma<<<g, 256, ATTN_SMEM>>>(pqf, pkf, pvth, pxf);
    }

    // 4) output projection (fp16 single-pass HMMA) -> d_out
    {
        dim3 g(HIDDEN / 128, MTOT / 128);       // (8, 64)
        hmma_gemm<<<g, 256, GEMM_SMEM>>>(pxf, pwo, b_out, out,
                                         nullptr, nullptr, nullptr,
                                         MTOT, HIDDEN, HIDDEN, 0);
    }
}

// round 17
// speedup vs baseline: 1.0736x; 1.0736x over previous
#include <cuda_runtime.h>
#include <cuda_bf16.h>
#include <cuda_fp16.h>
#include <math.h>
#include <stdint.h>

#define HIDDEN 1024
#define HEADS  16
#define HD     64
#define BATCH  4
#define SEQ    2048
#define MTOT   (BATCH * SEQ)   // 8192

// Q pre-scale: (1/sqrt(64)) * log2(e) -> softmax computed in exp2 domain
#define QSCALE 0.1803368801111244f

// ---------------- scratch (device globals; no allocs allowed) --------------
__device__ __half g_xf[MTOT * HIDDEN];            // activations fp16 (x, then attn out)
__device__ __half g_wq[3 * HIDDEN * HIDDEN];      // W_qkv^T fp16 [3072,1024]
__device__ __half g_wo[HIDDEN * HIDDEN];          // W_out^T fp16 [1024,1024]
__device__ __half g_qf[BATCH * HEADS * SEQ * HD]; // Q (pre-scaled, log2 domain)
__device__ __half g_kf[BATCH * HEADS * SEQ * HD]; // K
__device__ __half g_vth[BATCH * HEADS * HD * SEQ];// V^T

// ---------------- async-copy / ldmatrix helpers -----------------------------
__device__ __forceinline__ void cp_async16(uint32_t saddr, const void* gptr) {
    asm volatile("cp.async.ca.shared.global [%0], [%1], 16;"
                 :: "r"(saddr), "l"(gptr));
}
#define CP_COMMIT()  asm volatile("cp.async.commit_group;" ::: "memory")
#define CP_WAIT(n)   asm volatile("cp.async.wait_group %0;" :: "n"(n) : "memory")

__device__ __forceinline__ void ldsm4(uint32_t* r, uint32_t addr) {
    asm volatile("ldmatrix.sync.aligned.m8n8.x4.shared.b16 {%0,%1,%2,%3}, [%4];"
                 : "=r"(r[0]), "=r"(r[1]), "=r"(r[2]), "=r"(r[3]) : "r"(addr));
}

// ---------------------------------------------------------------------------
__global__ __launch_bounds__(256) void cast_kernel(
    const float* __restrict__ src, __half* __restrict__ dst, int n4)
{
    int i = blockIdx.x * blockDim.x + threadIdx.x;
    if (i >= n4) return;
    float4 v = ((const float4*)src)[i];
    ((__half2*)dst)[2 * i]     = __floats2half2_rn(v.x, v.y);
    ((__half2*)dst)[2 * i + 1] = __floats2half2_rn(v.z, v.w);
}

// transpose + cast: W[K,N] fp32 -> W^T fp16 [N,K]
__global__ void tcast_kernel(const float* __restrict__ W,
                             __half* __restrict__ Wt, int K, int N)
{
    __shared__ float t[32][33];
    int n0 = blockIdx.x * 32, k0 = blockIdx.y * 32;
    for (int r = threadIdx.y; r < 32; r += 8)
        t[r][threadIdx.x] = W[(size_t)(k0 + r) * N + n0 + threadIdx.x];
    __syncthreads();
    for (int r = threadIdx.y; r < 32; r += 8)
        Wt[(size_t)(n0 + r) * K + k0 + threadIdx.x] =
            __float2half_rn(t[threadIdx.x][r]);
}

// ---------------------------------------------------------------------------
__device__ __forceinline__ void mma16816h(float* c, const uint32_t* a, const uint32_t* b)
{
    asm volatile(
        "mma.sync.aligned.m16n8k16.row.col.f32.f16.f16.f32 "
        "{%0,%1,%2,%3}, {%4,%5,%6,%7}, {%8,%9}, {%0,%1,%2,%3};"
        : "+f"(c[0]), "+f"(c[1]), "+f"(c[2]), "+f"(c[3])
        : "r"(a[0]), "r"(a[1]), "r"(a[2]), "r"(a[3]), "r"(b[0]), "r"(b[1]));
}

// ---------------------------------------------------------------------------
// HMMA GEMM (single-pass fp16, R15 config): C[M,N] = A @ W^T + bias.
// A fp16 [M,K]; W fp16 [N,K]. CTA 128x128, 4 warps (2x2), warp tile 64x64.
// 128 threads, 2 CTAs/SM. cp.async 2-stage + ldmatrix.
// mode 0: C + bias (fp32). mode 1: QKV epilogue (Q scaled log2-domain, K, V^T).
// per stage: A=0 (10240B), B=10240; stage stride 20480.
// ---------------------------------------------------------------------------
#define SPAD 40
#define GST  20480
#define GEMM_SMEM (2 * GST)

__global__ __launch_bounds__(128, 2) void hmma_gemm(
    const __half* __restrict__ A, const __half* __restrict__ B,
    const float* __restrict__ bias, float* __restrict__ C,
    __half* __restrict__ qf, __half* __restrict__ kf,
    __half* __restrict__ vth,
    int M, int N, int K, int mode)
{
    extern __shared__ char smem[];
    const uint32_t sbase = (uint32_t)__cvta_generic_to_shared(smem);

    const int tid  = threadIdx.x;
    const int wid  = tid >> 5;
    const int lane = tid & 31;
    const int grp  = lane >> 2;
    const int tig  = lane & 3;
    const int wm   = wid & 1;
    const int wn   = wid >> 1;
    const int bm   = blockIdx.y * 128;
    const int bn   = blockIdx.x * 128;
    const int NT   = K / 32;

    const int mat = lane >> 3, lr = lane & 7;
    const int a_row = (mat & 1) * 8 + lr;
    const int a_col = (mat >> 1) * 8;
    const int b_jo  = mat >> 1;
    const int b_col = (mat & 1) * 8;

    float c[4][8][4];
    #pragma unroll
    for (int i = 0; i < 4; i++)
        #pragma unroll
        for (int j = 0; j < 8; j++)
            #pragma unroll
            for (int p = 0; p < 4; p++) c[i][j][p] = 0.f;

    auto issue_tile = [&](int kt, int stage) {
        const int k0 = kt * 32;
        const uint32_t st = sbase + stage * GST;
        #pragma unroll
        for (int u = 0; u < 4; u++) {
            int g = tid + u * 128;          // 0..511
            int r = g >> 2, ch = g & 3;
            uint32_t so = (uint32_t)(r * SPAD + ch * 8) * 2;
            cp_async16(st + so,         A + (size_t)(bm + r) * K + k0 + ch * 8);
            cp_async16(st + 10240 + so, B + (size_t)(bn + r) * K + k0 + ch * 8);
        }
        CP_COMMIT();
    };

    issue_tile(0, 0);

    for (int kt = 0; kt < NT; kt++) {
        if (kt + 1 < NT) {
            issue_tile(kt + 1, (kt + 1) & 1);
            CP_WAIT(1);
        } else {
            CP_WAIT(0);
        }
        __syncthreads();

        const uint32_t st = sbase + (kt & 1) * GST;

        #pragma unroll
        for (int ks = 0; ks < 2; ks++) {
            const int kk = ks * 16;
            uint32_t af[4][4], bf[4][4];
            #pragma unroll
            for (int i = 0; i < 4; i++) {
                uint32_t ad = st + (uint32_t)((wm * 64 + i * 16 + a_row) * SPAD + kk + a_col) * 2;
                ldsm4(af[i], ad);
            }
            #pragma unroll
            for (int p = 0; p < 4; p++) {
                uint32_t bd = st + 10240 +
                    (uint32_t)((wn * 64 + (p * 2 + b_jo) * 8 + lr) * SPAD + kk + b_col) * 2;
                ldsm4(bf[p], bd);
            }
            #pragma unroll
            for (int i = 0; i < 4; i++)
                #pragma unroll
                for (int j = 0; j < 8; j++)
                    mma16816h(c[i][j], af[i], &bf[j >> 1][(j & 1) * 2]);
        }
        __syncthreads();
    }

    #pragma unroll
    for (int i = 0; i < 4; i++) {
        #pragma unroll
        for (int j = 0; j < 8; j++) {
            int n0 = bn + wn * 64 + j * 8 + tig * 2;
            float2 bv = *(const float2*)(bias + n0);
            #pragma unroll
            for (int half = 0; half < 2; half++) {
                int m = bm + wm * 64 + i * 16 + grp + half * 8;
                float rx = c[i][j][half * 2 + 0] + bv.x;
                float ry = c[i][j][half * 2 + 1] + bv.y;
                if (mode == 0) {
                    *(float2*)(C + (size_t)m * N + n0) = make_float2(rx, ry);
                } else {
                    int sel = n0 >> 10, rem = n0 & 1023;
                    int h = rem >> 6, hd0 = rem & 63;
                    int b = m >> 11, s = m & 2047;
                    size_t bh_ = (size_t)b * HEADS + h;
                    if (sel == 0) {
                        size_t off = (bh_ * SEQ + s) * HD + hd0;
                        *(__half2*)(qf + off) =
                            __floats2half2_rn(rx * QSCALE, ry * QSCALE);
                    } else if (sel == 1) {
                        size_t off = (bh_ * SEQ + s) * HD + hd0;
                        *(__half2*)(kf + off) = __floats2half2_rn(rx, ry);
                    } else {
                        size_t o0 = (bh_ * HD + hd0) * SEQ + s;
                        size_t o1 = (bh_ * HD + hd0 + 1) * SEQ + s;
                        vth[o0] = __float2half_rn(rx);
                        vth[o1] = __float2half_rn(ry);
                    }
                }
            }
        }
    }
}

// ---------------------------------------------------------------------------
// fp16 HMMA flash attention (exp2 domain): 128 q-rows/CTA, 8 warps x 16
// q-rows, 64-key tiles, cp.async 2-stage + ldmatrix, 2 CTAs/SM.
// S' = (Q*log2e/8) * K ; P = exp2(S' - m'). Output fp16 [B,S,H*64].
// per stage: K=0 (9216B), V=9216; stage stride 18432.
// ---------------------------------------------------------------------------
#define KPITCH 72
#define AST    18432
#define ATTN_SMEM (2 * AST)

__global__ __launch_bounds__(256, 2) void attn_hmma(
    const __half* __restrict__ qf, const __half* __restrict__ kf,
    const __half* __restrict__ vth,
    __half* __restrict__ O)
{
    extern __shared__ char smem[];
    const uint32_t sbase = (uint32_t)__cvta_generic_to_shared(smem);

    const int tid  = threadIdx.x;
    const int wid  = tid >> 5;
    const int lane = tid & 31;
    const int grp  = lane >> 2;
    const int tig  = lane & 3;
    const int bh   = blockIdx.y;
    const int q0   = blockIdx.x * 128;

    const int mat = lane >> 3, lr = lane & 7;
    const int b_jo  = mat >> 1;
    const int b_col = (mat & 1) * 8;

    const __half* Kb = kf + (size_t)bh * SEQ * HD;
    const __half* Vb = vth + (size_t)bh * HD * SEQ;

    auto issue_tile = [&](int kt, int stage) {
        const uint32_t st = sbase + stage * AST;
        #pragma unroll
        for (int i = 0; i < 2; i++) {
            int g = tid + i * 256;
            int r = g >> 3, ch = g & 7;
            uint32_t so = (uint32_t)(r * KPITCH + ch * 8) * 2;
            cp_async16(st + so,        Kb + (size_t)(kt * 64 + r) * HD + ch * 8);
            cp_async16(st + 9216 + so, Vb + (size_t)r * SEQ + kt * 64 + ch * 8);
        }
        CP_COMMIT();
    };

    issue_tile(0, 0);

    uint32_t qfr[4][4];
    {
        const __half* Qp = qf + ((size_t)bh * SEQ + q0 + wid * 16) * HD;
        #pragma unroll
        for (int cc = 0; cc < 4; cc++) {
            int k0 = cc * 16 + 2 * tig;
            qfr[cc][0] = *(const uint32_t*)(Qp + grp * HD + k0);
            qfr[cc][1] = *(const uint32_t*)(Qp + (grp + 8) * HD + k0);
            qfr[cc][2] = *(const uint32_t*)(Qp + grp * HD + k0 + 8);
            qfr[cc][3] = *(const uint32_t*)(Qp + (grp + 8) * HD + k0 + 8);
        }
    }

    float o[8][4];
    #pragma unroll
    for (int j = 0; j < 8; j++)
        #pragma unroll
        for (int p = 0; p < 4; p++) o[j][p] = 0.f;
    float m0 = -INFINITY, m1 = -INFINITY, l0 = 0.f, l1 = 0.f;

    const int NT = SEQ / 64;
    for (int kt = 0; kt < NT; kt++) {
        if (kt + 1 < NT) {
            issue_tile(kt + 1, (kt + 1) & 1);
            CP_WAIT(1);
        } else {
            CP_WAIT(0);
        }
        __syncthreads();

        const uint32_t st = sbase + (kt & 1) * AST;

        // ---- S' = Q*K (log2 domain) ----
        float s[8][4];
        #pragma unroll
        for (int j = 0; j < 8; j++)
            #pragma unroll
            for (int p = 0; p < 4; p++) s[j][p] = 0.f;
        #pragma unroll
        for (int cc = 0; cc < 4; cc++) {
            #pragma unroll
            for (int p = 0; p < 4; p++) {
                uint32_t kfr[4];
                uint32_t kd = st + (uint32_t)(((p * 2 + b_jo) * 8 + lr) * KPITCH
                                              + cc * 16 + b_col) * 2;
                ldsm4(kfr, kd);
                mma16816h(s[2 * p],     qfr[cc], &kfr[0]);
                mma16816h(s[2 * p + 1], qfr[cc], &kfr[2]);
            }
        }

        // ---- online softmax (exp2) ----
        float mx0 = -INFINITY, mx1 = -INFINITY;
        #pragma unroll
        for (int j = 0; j < 8; j++) {
            mx0 = fmaxf(mx0, fmaxf(s[j][0], s[j][1]));
            mx1 = fmaxf(mx1, fmaxf(s[j][2], s[j][3]));
        }
        mx0 = fmaxf(mx0, __shfl_xor_sync(0xffffffffu, mx0, 1));
        mx0 = fmaxf(mx0, __shfl_xor_sync(0xffffffffu, mx0, 2));
        mx1 = fmaxf(mx1, __shfl_xor_sync(0xffffffffu, mx1, 1));
        mx1 = fmaxf(mx1, __shfl_xor_sync(0xffffffffu, mx1, 2));
        float mn0 = fmaxf(m0, mx0), mn1 = fmaxf(m1, mx1);
        float a0 = exp2f(m0 - mn0), a1 = exp2f(m1 - mn1);
        m0 = mn0; m1 = mn1;

        uint32_t pfr[4][4];
        float ps0 = 0.f, ps1 = 0.f;
        #pragma unroll
        for (int j = 0; j < 8; j++) {
            float p0 = exp2f(s[j][0] - m0);
            float p1 = exp2f(s[j][1] - m0);
            float p2 = exp2f(s[j][2] - m1);
            float p3 = exp2f(s[j][3] - m1);
            ps0 += p0 + p1;
            ps1 += p2 + p3;
            int cc = j >> 1, half = j & 1;
            __half2 pa = __floats2half2_rn(p0, p1);
            __half2 pb = __floats2half2_rn(p2, p3);
            pfr[cc][0 + 2 * half] = *(uint32_t*)&pa;
            pfr[cc][1 + 2 * half] = *(uint32_t*)&pb;
        }
        ps0 += __shfl_xor_sync(0xffffffffu, ps0, 1);
        ps0 += __shfl_xor_sync(0xffffffffu, ps0, 2);
        ps1 += __shfl_xor_sync(0xffffffffu, ps1, 1);
        ps1 += __shfl_xor_sync(0xffffffffu, ps1, 2);
        l0 = l0 * a0 + ps0;
        l1 = l1 * a1 + ps1;

        #pragma unroll
        for (int j = 0; j < 8; j++) {
            o[j][0] *= a0; o[j][1] *= a0;
            o[j][2] *= a1; o[j][3] *= a1;
        }

        // ---- O += P*V ----
        #pragma unroll
        for (int cc = 0; cc < 4; cc++) {
            #pragma unroll
            for (int p = 0; p < 4; p++) {
                uint32_t vfr[4];
                uint32_t vd = st + 9216 +
                    (uint32_t)(((p * 2 + b_jo) * 8 + lr) * KPITCH + cc * 16 + b_col) * 2;
                ldsm4(vfr, vd);
                mma16816h(o[2 * p],     pfr[cc], &vfr[0]);
                mma16816h(o[2 * p + 1], pfr[cc], &vfr[2]);
            }
        }
        __syncthreads();
    }

    // ---- epilogue: O / l, single fp16 into [B,S,H*64] ----
    const int b = bh >> 4;
    const int h = bh & 15;
    float inv0 = 1.0f / l0, inv1 = 1.0f / l1;
    int s0 = q0 + wid * 16 + grp;
    int s1 = s0 + 8;
    #pragma unroll
    for (int j = 0; j < 8; j++) {
        int col = h * HD + j * 8 + 2 * tig;
        size_t off0 = ((size_t)b * SEQ + s0) * HIDDEN + col;
        *(__half2*)(O + off0) = __floats2half2_rn(o[j][0] * inv0, o[j][1] * inv0);
        size_t off1 = ((size_t)b * SEQ + s1) * HIDDEN + col;
        *(__half2*)(O + off1) = __floats2half2_rn(o[j][2] * inv1, o[j][3] * inv1);
    }
}

// ---------------------------------------------------------------------------
extern "C" void kernel_launch(void* const* d_in, const int* in_sizes, int n_in,
                              void* d_out, int out_size)
{
    const float* x     = (const float*)d_in[0];
    const float* W_qkv = (const float*)d_in[1];
    const float* b_qkv = (const float*)d_in[2];
    const float* W_out = (const float*)d_in[3];
    const float* b_out = (const float*)d_in[4];
    float* out = (float*)d_out;

    static __half *pxf = nullptr, *pwq, *pwo;
    static __half *pqf, *pkf, *pvth;
    if (!pxf) {
        cudaGetSymbolAddress((void**)&pxf, g_xf);
        cudaGetSymbolAddress((void**)&pwq, g_wq);
        cudaGetSymbolAddress((void**)&pwo, g_wo);
        cudaGetSymbolAddress((void**)&pqf, g_qf);
        cudaGetSymbolAddress((void**)&pkf, g_kf);
        cudaGetSymbolAddress((void**)&pvth, g_vth);
        cudaFuncSetAttribute(hmma_gemm, cudaFuncAttributeMaxDynamicSharedMemorySize, GEMM_SMEM);
        cudaFuncSetAttribute(attn_hmma, cudaFuncAttributeMaxDynamicSharedMemorySize, ATTN_SMEM);
    }

    const int n4 = MTOT * HIDDEN / 4;

    // 1) cast x -> fp16; transpose+cast weights -> fp16
    cast_kernel<<<n4 / 256, 256>>>(x, pxf, n4);
    {
        dim3 g(3 * HIDDEN / 32, HIDDEN / 32);
        tcast_kernel<<<g, dim3(32, 8)>>>(W_qkv, pwq, HIDDEN, 3 * HIDDEN);
    }
    {
        dim3 g(HIDDEN / 32, HIDDEN / 32);
        tcast_kernel<<<g, dim3(32, 8)>>>(W_out, pwo, HIDDEN, HIDDEN);
    }

    // 2) QKV projection (fp16 single-pass HMMA, R15 config) -> Q/K/V fp16
    {
        dim3 g(3 * HIDDEN / 128, MTOT / 128);   // (24, 64)
        hmma_gemm<<<g, 128, GEMM_SMEM>>>(pxf, pwq, b_qkv, nullptr,
                                         pqf, pkf, pvth,
                                         MTOT, 3 * HIDDEN, HIDDEN, 1);
    }

    // 3) fp16 flash attention (exp2 domain) -> fp16 activations
    {
        dim3 g(SEQ / 128, BATCH * HEADS);       // (16, 64)
        attn_hmma<<<g, 256, ATTN_SMEM>>>(pqf, pkf, pvth, pxf);
    }

    // 4) output projection (fp16 single-pass HMMA) -> d_out
    {
        dim3 g(HIDDEN / 128, MTOT / 128);       // (8, 64)
        hmma_gemm<<<g, 128, GEMM_SMEM>>>(pxf, pwo, b_out, out,
                                         nullptr, nullptr, nullptr,
                                         MTOT, HIDDEN, HIDDEN, 0);
    }
}